// round 6
// baseline (speedup 1.0000x reference)
#include <cuda_runtime.h>
#include <cstdint>

#define NN      50000
#define NF      512
#define NHID1   256     // 8 heads * 32
#define NHID2   512     // 8 heads * 64
#define NCLS    64
#define NHEADS  8
#define C1      32
#define C2      64
#define E0      800000
#define NEG_SLOPE 0.2f

// ---------------- scratch (device globals; no allocs allowed) ----------------
__device__ float g_h1[(size_t)NN * NHID1];
__device__ float g_agg1[(size_t)NN * NHID1];
__device__ float g_h2[(size_t)NN * NHID2];
__device__ float g_agg2[(size_t)NN * NHID2];
__device__ float g_es[(size_t)NN * NHEADS];
__device__ float g_ed[(size_t)NN * NHEADS];
__device__ int   g_deg[NN];
__device__ int   g_off[NN + 1];
__device__ int   g_cur[NN];
__device__ int   g_csr[E0];                    // src indices sorted by dst

// ---------------- CSR build ----------------
__global__ void histogram_kernel(const int* __restrict__ ei, int* __restrict__ deg) {
    int e = blockIdx.x * blockDim.x + threadIdx.x;
    if (e >= E0) return;
    atomicAdd(deg + ei[E0 + e], 1);
}

__global__ void scan_kernel(const int* __restrict__ deg, int* __restrict__ off,
                            int* __restrict__ cur) {
    __shared__ int sh[1024];
    int t = threadIdx.x;
    const int CHUNK = (NN + 1023) / 1024;  // 49
    int beg = t * CHUNK;
    int end = min(beg + CHUNK, NN);
    int s = 0;
    for (int i = beg; i < end; i++) s += deg[i];
    sh[t] = s;
    __syncthreads();
    for (int st = 1; st < 1024; st <<= 1) {
        int a = (t >= st) ? sh[t - st] : 0;
        __syncthreads();
        sh[t] += a;
        __syncthreads();
    }
    int run = (t == 0) ? 0 : sh[t - 1];
    for (int i = beg; i < end; i++) {
        off[i] = run;
        cur[i] = run;
        run += deg[i];
    }
    if (t == 1023) off[NN] = E0;
}

__global__ void fill_kernel(const int* __restrict__ ei, int* __restrict__ cur,
                            int* __restrict__ csr) {
    int e = blockIdx.x * blockDim.x + threadIdx.x;
    if (e >= E0) return;
    int src = ei[e];
    int dst = ei[E0 + e];
    int pos = atomicAdd(cur + dst, 1);
    csr[pos] = src;
}

// ---------------- SGEMM: C[M,N] = A[M,K]*B[K,N], 128x128x16 tiles, 8x8/thread ----------------
__global__ void __launch_bounds__(256, 2)
sgemm128(const float* __restrict__ A, const float* __restrict__ B,
         float* __restrict__ C, int M, int K, int N) {
    __shared__ float As[16][128];
    __shared__ float Bs[16][128];
    int tid = threadIdx.x;
    int tx = tid & 15, ty = tid >> 4;
    int bm = blockIdx.y * 128, bn = blockIdx.x * 128;

    // A loads: 128 rows x 16 k  -> 2 float4 / thread
    int arow = tid >> 2;            // 0..63
    int ak = (tid & 3) * 4;
    // B loads: 16 rows x 128 cols -> 2 float4 / thread
    int brow = tid >> 5;            // 0..7
    int bcol = (tid & 31) * 4;

    const float* Ap0 = A + (size_t)(bm + arow) * K + ak;
    const float* Ap1 = A + (size_t)(bm + arow + 64) * K + ak;
    bool a0ok = (bm + arow) < M;
    bool a1ok = (bm + arow + 64) < M;

    float acc[8][8] = {};

    for (int k0 = 0; k0 < K; k0 += 16) {
        float4 a0 = a0ok ? *(const float4*)(Ap0 + k0) : make_float4(0.f, 0.f, 0.f, 0.f);
        float4 a1 = a1ok ? *(const float4*)(Ap1 + k0) : make_float4(0.f, 0.f, 0.f, 0.f);
        float4 bq0 = *(const float4*)(B + (size_t)(k0 + brow) * N + bn + bcol);
        float4 bq1 = *(const float4*)(B + (size_t)(k0 + brow + 8) * N + bn + bcol);

        As[ak + 0][arow] = a0.x; As[ak + 1][arow] = a0.y;
        As[ak + 2][arow] = a0.z; As[ak + 3][arow] = a0.w;
        As[ak + 0][arow + 64] = a1.x; As[ak + 1][arow + 64] = a1.y;
        As[ak + 2][arow + 64] = a1.z; As[ak + 3][arow + 64] = a1.w;
        *(float4*)&Bs[brow][bcol] = bq0;
        *(float4*)&Bs[brow + 8][bcol] = bq1;
        __syncthreads();

#pragma unroll
        for (int k = 0; k < 16; k++) {
            float4 av0 = *(float4*)&As[k][ty * 4];
            float4 av1 = *(float4*)&As[k][ty * 4 + 64];
            float4 bv0 = *(float4*)&Bs[k][tx * 4];
            float4 bv1 = *(float4*)&Bs[k][tx * 4 + 64];
            float av[8] = { av0.x, av0.y, av0.z, av0.w, av1.x, av1.y, av1.z, av1.w };
            float bv[8] = { bv0.x, bv0.y, bv0.z, bv0.w, bv1.x, bv1.y, bv1.z, bv1.w };
#pragma unroll
            for (int i = 0; i < 8; i++)
#pragma unroll
                for (int j = 0; j < 8; j++)
                    acc[i][j] += av[i] * bv[j];
        }
        __syncthreads();
    }

#pragma unroll
    for (int i = 0; i < 8; i++) {
        int row = bm + ty * 4 + (i & 3) + (i >> 2) * 64;
        if (row < M) {
            float4 o0 = make_float4(acc[i][0], acc[i][1], acc[i][2], acc[i][3]);
            float4 o1 = make_float4(acc[i][4], acc[i][5], acc[i][6], acc[i][7]);
            *(float4*)(C + (size_t)row * N + bn + tx * 4) = o0;
            *(float4*)(C + (size_t)row * N + bn + tx * 4 + 64) = o1;
        }
    }
}

// ---------------- per-node attention scores ----------------
template <int C>
__global__ void node_scores(const float* __restrict__ hbuf,
                            const float* __restrict__ asrc,
                            const float* __restrict__ adst,
                            float* __restrict__ es, float* __restrict__ ed) {
    int idx = blockIdx.x * blockDim.x + threadIdx.x;
    if (idx >= NN * NHEADS) return;
    int n = idx >> 3, h = idx & 7;
    const float* hp = hbuf + (size_t)n * NHEADS * C + h * C;
    const float* ap = asrc + h * C;
    const float* dp = adst + h * C;
    float s = 0.f, d = 0.f;
#pragma unroll
    for (int c = 0; c < C; c += 4) {
        float4 hv = *(const float4*)(hp + c);
        float4 av = *(const float4*)(ap + c);
        float4 dv = *(const float4*)(dp + c);
        s += hv.x * av.x + hv.y * av.y + hv.z * av.z + hv.w * av.w;
        d += hv.x * dv.x + hv.y * dv.y + hv.z * dv.z + hv.w * dv.w;
    }
    es[idx] = s;
    ed[idx] = d;
}

// ---------------- fused CSR aggregation (softmax folded, no atomics) ----------------
template <int C, int HID, bool RELU>
__global__ void gat_aggregate(const int* __restrict__ off, const int* __restrict__ csr,
                              const float* __restrict__ h,
                              const float* __restrict__ es, const float* __restrict__ ed,
                              const float* __restrict__ bias,
                              float* __restrict__ out) {
    constexpr int CPL = HID / 32;       // channels per lane (8 or 16)
    constexpr int NV = CPL / 4;         // float4s per lane (2 or 4)
    int lane = threadIdx.x & 31;
    int node = blockIdx.x * 8 + (threadIdx.x >> 5);
    if (node >= NN) return;
    int chbase = lane * CPL;
    int hd = chbase / C;

    float edv = __ldg(ed + (size_t)node * 8 + hd);

    // self loop seed
    float a = __ldg(es + (size_t)node * 8 + hd) + edv;
    a = (a > 0.f) ? a : NEG_SLOPE * a;
    float w = __expf(a);
    float z = w;
    float4 acc[NV];
    {
        const float4* hp = (const float4*)(h + (size_t)node * HID + chbase);
#pragma unroll
        for (int j = 0; j < NV; j++) {
            float4 v = __ldg(hp + j);
            acc[j] = make_float4(w * v.x, w * v.y, w * v.z, w * v.w);
        }
    }

    int beg = __ldg(off + node), end = __ldg(off + node + 1);
    for (int i = beg; i < end; i++) {
        int src = __ldg(csr + i);
        float av = __ldg(es + (size_t)src * 8 + hd) + edv;
        av = (av > 0.f) ? av : NEG_SLOPE * av;
        float we = __expf(av);
        z += we;
        const float4* sp = (const float4*)(h + (size_t)src * HID + chbase);
#pragma unroll
        for (int j = 0; j < NV; j++) {
            float4 v = __ldg(sp + j);
            acc[j].x += we * v.x; acc[j].y += we * v.y;
            acc[j].z += we * v.z; acc[j].w += we * v.w;
        }
    }

    float inv = 1.f / z;
    float4* op = (float4*)(out + (size_t)node * HID + chbase);
#pragma unroll
    for (int j = 0; j < NV; j++) {
        float4 o = make_float4(acc[j].x * inv, acc[j].y * inv,
                               acc[j].z * inv, acc[j].w * inv);
        if (RELU) {
            float4 b = *(const float4*)(bias + chbase + j * 4);
            o.x = fmaxf(o.x + b.x, 0.f);
            o.y = fmaxf(o.y + b.y, 0.f);
            o.z = fmaxf(o.z + b.z, 0.f);
            o.w = fmaxf(o.w + b.w, 0.f);
        }
        op[j] = o;
    }
}

// ---------------- head-mean + bias + log_softmax ----------------
__global__ void finalize_kernel(const float* __restrict__ agg2,
                                const float* __restrict__ b2,
                                float* __restrict__ out) {
    int n = blockIdx.x;
    int c = threadIdx.x;  // 64 threads
    float v = 0.f;
#pragma unroll
    for (int h = 0; h < NHEADS; h++) v += agg2[(size_t)n * NHID2 + h * NCLS + c];
    v = v * 0.125f + b2[c];
    __shared__ float sh[64];
    sh[c] = v;
    __syncthreads();
    for (int s = 32; s > 0; s >>= 1) {
        if (c < s) sh[c] = fmaxf(sh[c], sh[c + s]);
        __syncthreads();
    }
    float mx = sh[0];
    __syncthreads();
    sh[c] = __expf(v - mx);
    __syncthreads();
    for (int s = 32; s > 0; s >>= 1) {
        if (c < s) sh[c] += sh[c + s];
        __syncthreads();
    }
    out[(size_t)n * NCLS + c] = v - mx - logf(sh[0]);
}

// ---------------- launch ----------------
extern "C" void kernel_launch(void* const* d_in, const int* in_sizes, int n_in,
                              void* d_out, int out_size) {
    const float* x      = (const float*)d_in[0];
    const int*   ei     = (const int*)d_in[1];
    const float* W1     = (const float*)d_in[2];
    const float* a1_src = (const float*)d_in[3];
    const float* a1_dst = (const float*)d_in[4];
    const float* b1     = (const float*)d_in[5];
    const float* W2     = (const float*)d_in[6];
    const float* a2_src = (const float*)d_in[7];
    const float* a2_dst = (const float*)d_in[8];
    const float* b2     = (const float*)d_in[9];
    float* out = (float*)d_out;

    float *p_h1, *p_agg1, *p_h2, *p_agg2, *p_es, *p_ed;
    int *p_deg, *p_off, *p_cur, *p_csr;
    cudaGetSymbolAddress((void**)&p_h1,   g_h1);
    cudaGetSymbolAddress((void**)&p_agg1, g_agg1);
    cudaGetSymbolAddress((void**)&p_h2,   g_h2);
    cudaGetSymbolAddress((void**)&p_agg2, g_agg2);
    cudaGetSymbolAddress((void**)&p_es,   g_es);
    cudaGetSymbolAddress((void**)&p_ed,   g_ed);
    cudaGetSymbolAddress((void**)&p_deg,  g_deg);
    cudaGetSymbolAddress((void**)&p_off,  g_off);
    cudaGetSymbolAddress((void**)&p_cur,  g_cur);
    cudaGetSymbolAddress((void**)&p_csr,  g_csr);

    // ---------- CSR build (dst-sorted) ----------
    cudaMemsetAsync(p_deg, 0, NN * sizeof(int));
    histogram_kernel<<<(E0 + 255) / 256, 256>>>(ei, p_deg);
    scan_kernel<<<1, 1024>>>(p_deg, p_off, p_cur);
    fill_kernel<<<(E0 + 255) / 256, 256>>>(ei, p_cur, p_csr);

    // ---------- Layer 1 ----------
    {
        dim3 grid(NHID1 / 128, (NN + 127) / 128);
        sgemm128<<<grid, 256>>>(x, W1, p_h1, NN, NF, NHID1);
    }
    node_scores<C1><<<(NN * NHEADS + 255) / 256, 256>>>(p_h1, a1_src, a1_dst, p_es, p_ed);
    gat_aggregate<C1, NHID1, true><<<(NN + 7) / 8, 256>>>(p_off, p_csr, p_h1, p_es, p_ed, b1, p_agg1);

    // ---------- Layer 2 ----------
    {
        dim3 grid(NHID2 / 128, (NN + 127) / 128);
        sgemm128<<<grid, 256>>>(p_agg1, W2, p_h2, NN, NHID1, NHID2);
    }
    node_scores<C2><<<(NN * NHEADS + 255) / 256, 256>>>(p_h2, a2_src, a2_dst, p_es, p_ed);
    gat_aggregate<C2, NHID2, false><<<(NN + 7) / 8, 256>>>(p_off, p_csr, p_h2, p_es, p_ed, (const float*)nullptr, p_agg2);

    finalize_kernel<<<NN, NCLS>>>(p_agg2, b2, out);
}

// round 8
// speedup vs baseline: 2.3799x; 2.3799x over previous
#include <cuda_runtime.h>
#include <cstdint>

#define NN      50000
#define NF      512
#define NHID1   256     // 8 heads * 32
#define NHID2   512     // 8 heads * 64
#define NCLS    64
#define NHEADS  8
#define C1      32
#define C2      64
#define E0      800000
#define NEG_SLOPE 0.2f

// ---------------- scratch (device globals; no allocs allowed) ----------------
__device__ float g_h1[(size_t)NN * NHID1];
__device__ float g_agg1[(size_t)NN * NHID1];
__device__ float g_h2[(size_t)NN * NHID2];
__device__ float g_agg2[(size_t)NN * NHID2];
__device__ float g_es[(size_t)NN * NHEADS];
__device__ float g_ed[(size_t)NN * NHEADS];
__device__ int   g_deg[NN];
__device__ int   g_off[NN + 1];
__device__ int   g_cur[NN];
__device__ int   g_csr[E0];                    // src indices sorted by dst

// ---------------- CSR build ----------------
__global__ void histogram_kernel(const int* __restrict__ ei, int* __restrict__ deg) {
    int e = blockIdx.x * blockDim.x + threadIdx.x;
    if (e >= E0) return;
    atomicAdd(deg + ei[E0 + e], 1);
}

__global__ void scan_kernel(const int* __restrict__ deg, int* __restrict__ off,
                            int* __restrict__ cur) {
    __shared__ int sh[1024];
    int t = threadIdx.x;
    const int CHUNK = (NN + 1023) / 1024;  // 49
    int beg = t * CHUNK;
    int end = min(beg + CHUNK, NN);
    int s = 0;
    for (int i = beg; i < end; i++) s += deg[i];
    sh[t] = s;
    __syncthreads();
    for (int st = 1; st < 1024; st <<= 1) {
        int a = (t >= st) ? sh[t - st] : 0;
        __syncthreads();
        sh[t] += a;
        __syncthreads();
    }
    int run = (t == 0) ? 0 : sh[t - 1];
    for (int i = beg; i < end; i++) {
        off[i] = run;
        cur[i] = run;
        run += deg[i];
    }
    if (t == 1023) off[NN] = E0;
}

__global__ void fill_kernel(const int* __restrict__ ei, int* __restrict__ cur,
                            int* __restrict__ csr) {
    int e = blockIdx.x * blockDim.x + threadIdx.x;
    if (e >= E0) return;
    int src = ei[e];
    int dst = ei[E0 + e];
    int pos = atomicAdd(cur + dst, 1);
    csr[pos] = src;
}

// ---------------- tf32 tensor-core GEMM (plain-LDS fragments, no ldmatrix) ----------------
__device__ __forceinline__ uint32_t f2tf32(float f) {
    uint32_t u;
    asm("cvt.rna.tf32.f32 %0, %1;" : "=r"(u) : "f"(f));
    return u;
}

__device__ __forceinline__ void mma_tf32(float4& d, const uint32_t* a, const uint32_t* b) {
    asm volatile("mma.sync.aligned.m16n8k8.row.col.f32.tf32.tf32.f32 "
                 "{%0,%1,%2,%3}, {%4,%5,%6,%7}, {%8,%9}, {%0,%1,%2,%3};"
                 : "+f"(d.x), "+f"(d.y), "+f"(d.z), "+f"(d.w)
                 : "r"(a[0]), "r"(a[1]), "r"(a[2]), "r"(a[3]), "r"(b[0]), "r"(b[1]));
}

// C[M,N] = A[M,K]*B[K,N]; 128x128x32 block tiles, 8 warps, warp tile 64x32.
// As[m=128][k=32] stride 37 (37%32=5 -> conflict-free loads AND stores).
// Bs[k=32][n=128] stride 136 (136%32=8 -> conflict-free fragment loads; STS.128 fills).
#define AS_STRIDE 37
#define BS_STRIDE 136
__global__ void __launch_bounds__(256, 2)
tf32gemm(const float* __restrict__ A, const float* __restrict__ B,
         float* __restrict__ C, int M, int K, int N) {
    __shared__ uint32_t As[128 * AS_STRIDE];
    __shared__ uint32_t Bs[32 * BS_STRIDE];
    int tid = threadIdx.x;
    int lane = tid & 31;
    int warp = tid >> 5;
    int wm = warp & 1;            // m-offset 0/64
    int wn = warp >> 1;           // n-offset 0/32/64/96
    int bm = blockIdx.y * 128, bn = blockIdx.x * 128;

    int gid = lane >> 2;          // groupID 0..7
    int tig = lane & 3;           // threadID_in_group 0..3

    float4 acc[4][4];
#pragma unroll
    for (int i = 0; i < 4; i++)
#pragma unroll
        for (int j = 0; j < 4; j++) acc[i][j] = make_float4(0.f, 0.f, 0.f, 0.f);

    for (int k0 = 0; k0 < K; k0 += 32) {
        // ---- fill A tile: 128 rows x 32 k (scalar tf32 stores, conflict-free) ----
#pragma unroll
        for (int p = 0; p < 4; p++) {
            int row = (tid >> 3) + p * 32;
            int col = (tid & 7) * 4;
            float4 v = make_float4(0.f, 0.f, 0.f, 0.f);
            if (bm + row < M)
                v = *(const float4*)(A + (size_t)(bm + row) * K + k0 + col);
            uint32_t* dst = &As[row * AS_STRIDE + col];
            dst[0] = f2tf32(v.x); dst[1] = f2tf32(v.y);
            dst[2] = f2tf32(v.z); dst[3] = f2tf32(v.w);
        }
        // ---- fill B tile: 32 k x 128 n (vectorized stores) ----
#pragma unroll
        for (int p = 0; p < 4; p++) {
            int k = p * 8 + (tid >> 5);
            int n4 = (tid & 31) * 4;
            float4 v = *(const float4*)(B + (size_t)(k0 + k) * N + bn + n4);
            uint4 t;
            t.x = f2tf32(v.x); t.y = f2tf32(v.y);
            t.z = f2tf32(v.z); t.w = f2tf32(v.w);
            *(uint4*)&Bs[k * BS_STRIDE + n4] = t;
        }
        __syncthreads();

#pragma unroll
        for (int kk = 0; kk < 32; kk += 8) {
            uint32_t af[4][4];   // 4 m-tiles (16 rows each)
            uint32_t bf[4][2];   // 4 n-tiles (8 cols each)
#pragma unroll
            for (int mt = 0; mt < 4; mt++) {
                int m = wm * 64 + mt * 16;
                const uint32_t* a0 = &As[(m + gid) * AS_STRIDE + kk + tig];
                const uint32_t* a1 = &As[(m + gid + 8) * AS_STRIDE + kk + tig];
                af[mt][0] = a0[0];
                af[mt][1] = a1[0];
                af[mt][2] = a0[4];
                af[mt][3] = a1[4];
            }
#pragma unroll
            for (int nt = 0; nt < 4; nt++) {
                int n = wn * 32 + nt * 8;
                bf[nt][0] = Bs[(kk + tig) * BS_STRIDE + n + gid];
                bf[nt][1] = Bs[(kk + tig + 4) * BS_STRIDE + n + gid];
            }
#pragma unroll
            for (int mt = 0; mt < 4; mt++)
#pragma unroll
                for (int nt = 0; nt < 4; nt++)
                    mma_tf32(acc[mt][nt], af[mt], bf[nt]);
        }
        __syncthreads();
    }

    // ---- epilogue (c0/c1: row=gid, cols 2*tig..; c2/c3: row+8) ----
#pragma unroll
    for (int mt = 0; mt < 4; mt++) {
        int row0 = bm + wm * 64 + mt * 16 + gid;
        int row1 = row0 + 8;
#pragma unroll
        for (int nt = 0; nt < 4; nt++) {
            int col = bn + wn * 32 + nt * 8 + tig * 2;
            if (row0 < M)
                *(float2*)(C + (size_t)row0 * N + col) = make_float2(acc[mt][nt].x, acc[mt][nt].y);
            if (row1 < M)
                *(float2*)(C + (size_t)row1 * N + col) = make_float2(acc[mt][nt].z, acc[mt][nt].w);
        }
    }
}

// ---------------- per-node attention scores ----------------
template <int C>
__global__ void node_scores(const float* __restrict__ hbuf,
                            const float* __restrict__ asrc,
                            const float* __restrict__ adst,
                            float* __restrict__ es, float* __restrict__ ed) {
    int idx = blockIdx.x * blockDim.x + threadIdx.x;
    if (idx >= NN * NHEADS) return;
    int n = idx >> 3, h = idx & 7;
    const float* hp = hbuf + (size_t)n * NHEADS * C + h * C;
    const float* ap = asrc + h * C;
    const float* dp = adst + h * C;
    float s = 0.f, d = 0.f;
#pragma unroll
    for (int c = 0; c < C; c += 4) {
        float4 hv = *(const float4*)(hp + c);
        float4 av = *(const float4*)(ap + c);
        float4 dv = *(const float4*)(dp + c);
        s += hv.x * av.x + hv.y * av.y + hv.z * av.z + hv.w * av.w;
        d += hv.x * dv.x + hv.y * dv.y + hv.z * dv.z + hv.w * dv.w;
    }
    es[idx] = s;
    ed[idx] = d;
}

// ---------------- fused CSR aggregation (softmax folded, no atomics) ----------------
template <int C, int HID, bool RELU>
__global__ void gat_aggregate(const int* __restrict__ off, const int* __restrict__ csr,
                              const float* __restrict__ h,
                              const float* __restrict__ es, const float* __restrict__ ed,
                              const float* __restrict__ bias,
                              float* __restrict__ out) {
    constexpr int CPL = HID / 32;       // channels per lane (8 or 16)
    constexpr int NV = CPL / 4;         // float4s per lane (2 or 4)
    int lane = threadIdx.x & 31;
    int node = blockIdx.x * 8 + (threadIdx.x >> 5);
    if (node >= NN) return;
    int chbase = lane * CPL;
    int hd = chbase / C;

    float edv = __ldg(ed + (size_t)node * 8 + hd);

    // self loop seed
    float a = __ldg(es + (size_t)node * 8 + hd) + edv;
    a = (a > 0.f) ? a : NEG_SLOPE * a;
    float w = __expf(a);
    float z = w;
    float4 acc[NV];
    {
        const float4* hp = (const float4*)(h + (size_t)node * HID + chbase);
#pragma unroll
        for (int j = 0; j < NV; j++) {
            float4 v = __ldg(hp + j);
            acc[j] = make_float4(w * v.x, w * v.y, w * v.z, w * v.w);
        }
    }

    int beg = __ldg(off + node), end = __ldg(off + node + 1);
    for (int i = beg; i < end; i++) {
        int src = __ldg(csr + i);
        float av = __ldg(es + (size_t)src * 8 + hd) + edv;
        av = (av > 0.f) ? av : NEG_SLOPE * av;
        float we = __expf(av);
        z += we;
        const float4* sp = (const float4*)(h + (size_t)src * HID + chbase);
#pragma unroll
        for (int j = 0; j < NV; j++) {
            float4 v = __ldg(sp + j);
            acc[j].x += we * v.x; acc[j].y += we * v.y;
            acc[j].z += we * v.z; acc[j].w += we * v.w;
        }
    }

    float inv = 1.f / z;
    float4* op = (float4*)(out + (size_t)node * HID + chbase);
#pragma unroll
    for (int j = 0; j < NV; j++) {
        float4 o = make_float4(acc[j].x * inv, acc[j].y * inv,
                               acc[j].z * inv, acc[j].w * inv);
        if (RELU) {
            float4 b = *(const float4*)(bias + chbase + j * 4);
            o.x = fmaxf(o.x + b.x, 0.f);
            o.y = fmaxf(o.y + b.y, 0.f);
            o.z = fmaxf(o.z + b.z, 0.f);
            o.w = fmaxf(o.w + b.w, 0.f);
        }
        op[j] = o;
    }
}

// ---------------- head-mean + bias + log_softmax ----------------
__global__ void finalize_kernel(const float* __restrict__ agg2,
                                const float* __restrict__ b2,
                                float* __restrict__ out) {
    int n = blockIdx.x;
    int c = threadIdx.x;  // 64 threads
    float v = 0.f;
#pragma unroll
    for (int h = 0; h < NHEADS; h++) v += agg2[(size_t)n * NHID2 + h * NCLS + c];
    v = v * 0.125f + b2[c];
    __shared__ float sh[64];
    sh[c] = v;
    __syncthreads();
    for (int s = 32; s > 0; s >>= 1) {
        if (c < s) sh[c] = fmaxf(sh[c], sh[c + s]);
        __syncthreads();
    }
    float mx = sh[0];
    __syncthreads();
    sh[c] = __expf(v - mx);
    __syncthreads();
    for (int s = 32; s > 0; s >>= 1) {
        if (c < s) sh[c] += sh[c + s];
        __syncthreads();
    }
    out[(size_t)n * NCLS + c] = v - mx - logf(sh[0]);
}

// ---------------- launch ----------------
extern "C" void kernel_launch(void* const* d_in, const int* in_sizes, int n_in,
                              void* d_out, int out_size) {
    const float* x      = (const float*)d_in[0];
    const int*   ei     = (const int*)d_in[1];
    const float* W1     = (const float*)d_in[2];
    const float* a1_src = (const float*)d_in[3];
    const float* a1_dst = (const float*)d_in[4];
    const float* b1     = (const float*)d_in[5];
    const float* W2     = (const float*)d_in[6];
    const float* a2_src = (const float*)d_in[7];
    const float* a2_dst = (const float*)d_in[8];
    const float* b2     = (const float*)d_in[9];
    float* out = (float*)d_out;

    float *p_h1, *p_agg1, *p_h2, *p_agg2, *p_es, *p_ed;
    int *p_deg, *p_off, *p_cur, *p_csr;
    cudaGetSymbolAddress((void**)&p_h1,   g_h1);
    cudaGetSymbolAddress((void**)&p_agg1, g_agg1);
    cudaGetSymbolAddress((void**)&p_h2,   g_h2);
    cudaGetSymbolAddress((void**)&p_agg2, g_agg2);
    cudaGetSymbolAddress((void**)&p_es,   g_es);
    cudaGetSymbolAddress((void**)&p_ed,   g_ed);
    cudaGetSymbolAddress((void**)&p_deg,  g_deg);
    cudaGetSymbolAddress((void**)&p_off,  g_off);
    cudaGetSymbolAddress((void**)&p_cur,  g_cur);
    cudaGetSymbolAddress((void**)&p_csr,  g_csr);

    // ---------- CSR build (dst-sorted) ----------
    cudaMemsetAsync(p_deg, 0, NN * sizeof(int));
    histogram_kernel<<<(E0 + 255) / 256, 256>>>(ei, p_deg);
    scan_kernel<<<1, 1024>>>(p_deg, p_off, p_cur);
    fill_kernel<<<(E0 + 255) / 256, 256>>>(ei, p_cur, p_csr);

    // ---------- Layer 1 ----------
    {
        dim3 grid(NHID1 / 128, (NN + 127) / 128);
        tf32gemm<<<grid, 256>>>(x, W1, p_h1, NN, NF, NHID1);
    }
    node_scores<C1><<<(NN * NHEADS + 255) / 256, 256>>>(p_h1, a1_src, a1_dst, p_es, p_ed);
    gat_aggregate<C1, NHID1, true><<<(NN + 7) / 8, 256>>>(p_off, p_csr, p_h1, p_es, p_ed, b1, p_agg1);

    // ---------- Layer 2 ----------
    {
        dim3 grid(NHID2 / 128, (NN + 127) / 128);
        tf32gemm<<<grid, 256>>>(p_agg1, W2, p_h2, NN, NHID1, NHID2);
    }
    node_scores<C2><<<(NN * NHEADS + 255) / 256, 256>>>(p_h2, a2_src, a2_dst, p_es, p_ed);
    gat_aggregate<C2, NHID2, false><<<(NN + 7) / 8, 256>>>(p_off, p_csr, p_h2, p_es, p_ed, (const float*)nullptr, p_agg2);

    finalize_kernel<<<NN, NCLS>>>(p_agg2, b2, out);
}

// round 9
// speedup vs baseline: 3.0784x; 1.2935x over previous
#include <cuda_runtime.h>
#include <cuda_fp16.h>
#include <cstdint>

#define NN      50000
#define NF      512
#define NHID1   256     // 8 heads * 32
#define NHID2   512     // 8 heads * 64
#define NCLS    64
#define NHEADS  8
#define C1      32
#define C2      64
#define E0      800000
#define NEG_SLOPE 0.2f

// ---------------- scratch (device globals; no allocs allowed) ----------------
__device__ __half g_h1[(size_t)NN * NHID1];
__device__ float  g_agg1[(size_t)NN * NHID1];
__device__ __half g_h2[(size_t)NN * NHID2];
__device__ float  g_es[(size_t)NN * NHEADS];
__device__ float  g_ed[(size_t)NN * NHEADS];
__device__ int    g_deg[NN];
__device__ int    g_off[NN + 1];
__device__ int    g_cur[NN];
__device__ int    g_csr[E0];                   // src indices sorted by dst

// ---------------- CSR build ----------------
__global__ void histogram_kernel(const int* __restrict__ ei, int* __restrict__ deg) {
    int e = blockIdx.x * blockDim.x + threadIdx.x;
    if (e >= E0) return;
    atomicAdd(deg + ei[E0 + e], 1);
}

__global__ void scan_kernel(const int* __restrict__ deg, int* __restrict__ off,
                            int* __restrict__ cur) {
    __shared__ int sh[1024];
    int t = threadIdx.x;
    const int CHUNK = (NN + 1023) / 1024;  // 49
    int beg = t * CHUNK;
    int end = min(beg + CHUNK, NN);
    int s = 0;
    for (int i = beg; i < end; i++) s += deg[i];
    sh[t] = s;
    __syncthreads();
    for (int st = 1; st < 1024; st <<= 1) {
        int a = (t >= st) ? sh[t - st] : 0;
        __syncthreads();
        sh[t] += a;
        __syncthreads();
    }
    int run = (t == 0) ? 0 : sh[t - 1];
    for (int i = beg; i < end; i++) {
        off[i] = run;
        cur[i] = run;
        run += deg[i];
    }
    if (t == 1023) off[NN] = E0;
}

__global__ void fill_kernel(const int* __restrict__ ei, int* __restrict__ cur,
                            int* __restrict__ csr) {
    int e = blockIdx.x * blockDim.x + threadIdx.x;
    if (e >= E0) return;
    int src = ei[e];
    int dst = ei[E0 + e];
    int pos = atomicAdd(cur + dst, 1);
    csr[pos] = src;
}

// ---------------- tf32 tensor-core GEMM (plain-LDS fragments), fp16 output ----------------
__device__ __forceinline__ uint32_t f2tf32(float f) {
    uint32_t u;
    asm("cvt.rna.tf32.f32 %0, %1;" : "=r"(u) : "f"(f));
    return u;
}

__device__ __forceinline__ void mma_tf32(float4& d, const uint32_t* a, const uint32_t* b) {
    asm volatile("mma.sync.aligned.m16n8k8.row.col.f32.tf32.tf32.f32 "
                 "{%0,%1,%2,%3}, {%4,%5,%6,%7}, {%8,%9}, {%0,%1,%2,%3};"
                 : "+f"(d.x), "+f"(d.y), "+f"(d.z), "+f"(d.w)
                 : "r"(a[0]), "r"(a[1]), "r"(a[2]), "r"(a[3]), "r"(b[0]), "r"(b[1]));
}

// C[M,N](fp16) = A[M,K]*B[K,N]; 128x128x32 tiles, 8 warps, warp tile 64x32.
#define AS_STRIDE 37
#define BS_STRIDE 136
__global__ void __launch_bounds__(256, 2)
tf32gemm(const float* __restrict__ A, const float* __restrict__ B,
         __half* __restrict__ C, int M, int K, int N) {
    __shared__ uint32_t As[128 * AS_STRIDE];
    __shared__ uint32_t Bs[32 * BS_STRIDE];
    int tid = threadIdx.x;
    int lane = tid & 31;
    int warp = tid >> 5;
    int wm = warp & 1;
    int wn = warp >> 1;
    int bm = blockIdx.y * 128, bn = blockIdx.x * 128;

    int gid = lane >> 2;
    int tig = lane & 3;

    float4 acc[4][4];
#pragma unroll
    for (int i = 0; i < 4; i++)
#pragma unroll
        for (int j = 0; j < 4; j++) acc[i][j] = make_float4(0.f, 0.f, 0.f, 0.f);

    for (int k0 = 0; k0 < K; k0 += 32) {
#pragma unroll
        for (int p = 0; p < 4; p++) {
            int row = (tid >> 3) + p * 32;
            int col = (tid & 7) * 4;
            float4 v = make_float4(0.f, 0.f, 0.f, 0.f);
            if (bm + row < M)
                v = *(const float4*)(A + (size_t)(bm + row) * K + k0 + col);
            uint32_t* dst = &As[row * AS_STRIDE + col];
            dst[0] = f2tf32(v.x); dst[1] = f2tf32(v.y);
            dst[2] = f2tf32(v.z); dst[3] = f2tf32(v.w);
        }
#pragma unroll
        for (int p = 0; p < 4; p++) {
            int k = p * 8 + (tid >> 5);
            int n4 = (tid & 31) * 4;
            float4 v = *(const float4*)(B + (size_t)(k0 + k) * N + bn + n4);
            uint4 t;
            t.x = f2tf32(v.x); t.y = f2tf32(v.y);
            t.z = f2tf32(v.z); t.w = f2tf32(v.w);
            *(uint4*)&Bs[k * BS_STRIDE + n4] = t;
        }
        __syncthreads();

#pragma unroll
        for (int kk = 0; kk < 32; kk += 8) {
            uint32_t af[4][4];
            uint32_t bf[4][2];
#pragma unroll
            for (int mt = 0; mt < 4; mt++) {
                int m = wm * 64 + mt * 16;
                const uint32_t* a0 = &As[(m + gid) * AS_STRIDE + kk + tig];
                const uint32_t* a1 = &As[(m + gid + 8) * AS_STRIDE + kk + tig];
                af[mt][0] = a0[0];
                af[mt][1] = a1[0];
                af[mt][2] = a0[4];
                af[mt][3] = a1[4];
            }
#pragma unroll
            for (int nt = 0; nt < 4; nt++) {
                int n = wn * 32 + nt * 8;
                bf[nt][0] = Bs[(kk + tig) * BS_STRIDE + n + gid];
                bf[nt][1] = Bs[(kk + tig + 4) * BS_STRIDE + n + gid];
            }
#pragma unroll
            for (int mt = 0; mt < 4; mt++)
#pragma unroll
                for (int nt = 0; nt < 4; nt++)
                    mma_tf32(acc[mt][nt], af[mt], bf[nt]);
        }
        __syncthreads();
    }

#pragma unroll
    for (int mt = 0; mt < 4; mt++) {
        int row0 = bm + wm * 64 + mt * 16 + gid;
        int row1 = row0 + 8;
#pragma unroll
        for (int nt = 0; nt < 4; nt++) {
            int col = bn + wn * 32 + nt * 8 + tig * 2;
            if (row0 < M)
                *(__half2*)(C + (size_t)row0 * N + col) = __floats2half2_rn(acc[mt][nt].x, acc[mt][nt].y);
            if (row1 < M)
                *(__half2*)(C + (size_t)row1 * N + col) = __floats2half2_rn(acc[mt][nt].z, acc[mt][nt].w);
        }
    }
}

// ---------------- per-node attention scores (fp16 h) ----------------
template <int C>
__global__ void node_scores(const __half* __restrict__ hbuf,
                            const float* __restrict__ asrc,
                            const float* __restrict__ adst,
                            float* __restrict__ es, float* __restrict__ ed) {
    int idx = blockIdx.x * blockDim.x + threadIdx.x;
    if (idx >= NN * NHEADS) return;
    int n = idx >> 3, h = idx & 7;
    const __half2* hp = (const __half2*)(hbuf + (size_t)n * NHEADS * C + h * C);
    const float* ap = asrc + h * C;
    const float* dp = adst + h * C;
    float s = 0.f, d = 0.f;
#pragma unroll
    for (int c = 0; c < C / 2; c++) {
        float2 hv = __half22float2(hp[c]);
        s += hv.x * ap[2 * c] + hv.y * ap[2 * c + 1];
        d += hv.x * dp[2 * c] + hv.y * dp[2 * c + 1];
    }
    es[idx] = s;
    ed[idx] = d;
}

// ---------------- fused CSR aggregation (fp16 gather, fp32 accumulate) ----------------
// MODE 0: out fp32 = relu(agg + bias)        (layer 1)
// MODE 1: head-mean + bias + log_softmax fused in-warp, write final output (layer 2)
template <int C, int HID, int MODE>
__global__ void gat_aggregate(const int* __restrict__ off, const int* __restrict__ csr,
                              const __half* __restrict__ h,
                              const float* __restrict__ es, const float* __restrict__ ed,
                              const float* __restrict__ bias,
                              float* __restrict__ out) {
    constexpr int CPL = HID / 32;       // channels per lane (8 or 16)
    constexpr int NH = CPL / 8;         // uint4 (8 halves) per lane (1 or 2)
    int lane = threadIdx.x & 31;
    int node = blockIdx.x * 8 + (threadIdx.x >> 5);
    if (node >= NN) return;
    int chbase = lane * CPL;
    int hd = chbase / C;

    float edv = __ldg(ed + (size_t)node * 8 + hd);

    // self loop seed
    float a = __ldg(es + (size_t)node * 8 + hd) + edv;
    a = (a > 0.f) ? a : NEG_SLOPE * a;
    float w = __expf(a);
    float z = w;
    float acc[CPL];
    {
        const uint4* hp = (const uint4*)(h + (size_t)node * HID + chbase);
#pragma unroll
        for (int j = 0; j < NH; j++) {
            uint4 raw = __ldg(hp + j);
            const __half2* hh = (const __half2*)&raw;
#pragma unroll
            for (int q = 0; q < 4; q++) {
                float2 f = __half22float2(hh[q]);
                acc[j * 8 + 2 * q]     = w * f.x;
                acc[j * 8 + 2 * q + 1] = w * f.y;
            }
        }
    }

    int beg = __ldg(off + node), end = __ldg(off + node + 1);
    for (int i = beg; i < end; i++) {
        int src = __ldg(csr + i);
        float av = __ldg(es + (size_t)src * 8 + hd) + edv;
        av = (av > 0.f) ? av : NEG_SLOPE * av;
        float we = __expf(av);
        z += we;
        const uint4* sp = (const uint4*)(h + (size_t)src * HID + chbase);
#pragma unroll
        for (int j = 0; j < NH; j++) {
            uint4 raw = __ldg(sp + j);
            const __half2* hh = (const __half2*)&raw;
#pragma unroll
            for (int q = 0; q < 4; q++) {
                float2 f = __half22float2(hh[q]);
                acc[j * 8 + 2 * q]     += we * f.x;
                acc[j * 8 + 2 * q + 1] += we * f.y;
            }
        }
    }

    float inv = 1.f / z;

    if (MODE == 0) {
        // bias + relu, fp32 out
        float4* op = (float4*)(out + (size_t)node * HID + chbase);
#pragma unroll
        for (int j = 0; j < CPL / 4; j++) {
            float4 b = *(const float4*)(bias + chbase + j * 4);
            float4 o;
            o.x = fmaxf(acc[j * 4 + 0] * inv + b.x, 0.f);
            o.y = fmaxf(acc[j * 4 + 1] * inv + b.y, 0.f);
            o.z = fmaxf(acc[j * 4 + 2] * inv + b.z, 0.f);
            o.w = fmaxf(acc[j * 4 + 3] * inv + b.w, 0.f);
            op[j] = o;
        }
    } else {
        // ---- fused: head mean + bias + log_softmax (CPL==16, C==64) ----
        // lane L holds channels [16L,16L+16) = head L/4, classes 16*(L&3)+idx
        float v[16];
#pragma unroll
        for (int idx = 0; idx < 16; idx++) v[idx] = acc[idx] * inv;
        // sum over 8 heads: lanes {L, L^4, L^8, L^16, ...} hold same classes
#pragma unroll
        for (int m = 4; m <= 16; m <<= 1)
#pragma unroll
            for (int idx = 0; idx < 16; idx++)
                v[idx] += __shfl_xor_sync(0xffffffffu, v[idx], m);
        int mcls = (lane & 3) * 16;
#pragma unroll
        for (int idx = 0; idx < 16; idx++)
            v[idx] = v[idx] * 0.125f + __ldg(bias + mcls + idx);
        // max over all 64 classes (nibble = 4 distinct class groups)
        float mx = v[0];
#pragma unroll
        for (int idx = 1; idx < 16; idx++) mx = fmaxf(mx, v[idx]);
        mx = fmaxf(mx, __shfl_xor_sync(0xffffffffu, mx, 1));
        mx = fmaxf(mx, __shfl_xor_sync(0xffffffffu, mx, 2));
        float s = 0.f;
#pragma unroll
        for (int idx = 0; idx < 16; idx++) s += __expf(v[idx] - mx);
        s += __shfl_xor_sync(0xffffffffu, s, 1);
        s += __shfl_xor_sync(0xffffffffu, s, 2);
        float lg = mx + logf(s);
        if (lane < 4) {
            float4* op = (float4*)(out + (size_t)node * NCLS + lane * 16);
#pragma unroll
            for (int j = 0; j < 4; j++)
                op[j] = make_float4(v[j * 4] - lg, v[j * 4 + 1] - lg,
                                    v[j * 4 + 2] - lg, v[j * 4 + 3] - lg);
        }
    }
}

// ---------------- launch ----------------
extern "C" void kernel_launch(void* const* d_in, const int* in_sizes, int n_in,
                              void* d_out, int out_size) {
    const float* x      = (const float*)d_in[0];
    const int*   ei     = (const int*)d_in[1];
    const float* W1     = (const float*)d_in[2];
    const float* a1_src = (const float*)d_in[3];
    const float* a1_dst = (const float*)d_in[4];
    const float* b1     = (const float*)d_in[5];
    const float* W2     = (const float*)d_in[6];
    const float* a2_src = (const float*)d_in[7];
    const float* a2_dst = (const float*)d_in[8];
    const float* b2     = (const float*)d_in[9];
    float* out = (float*)d_out;

    __half *p_h1, *p_h2;
    float *p_agg1, *p_es, *p_ed;
    int *p_deg, *p_off, *p_cur, *p_csr;
    cudaGetSymbolAddress((void**)&p_h1,   g_h1);
    cudaGetSymbolAddress((void**)&p_agg1, g_agg1);
    cudaGetSymbolAddress((void**)&p_h2,   g_h2);
    cudaGetSymbolAddress((void**)&p_es,   g_es);
    cudaGetSymbolAddress((void**)&p_ed,   g_ed);
    cudaGetSymbolAddress((void**)&p_deg,  g_deg);
    cudaGetSymbolAddress((void**)&p_off,  g_off);
    cudaGetSymbolAddress((void**)&p_cur,  g_cur);
    cudaGetSymbolAddress((void**)&p_csr,  g_csr);

    // ---------- CSR build (dst-sorted) ----------
    cudaMemsetAsync(p_deg, 0, NN * sizeof(int));
    histogram_kernel<<<(E0 + 255) / 256, 256>>>(ei, p_deg);
    scan_kernel<<<1, 1024>>>(p_deg, p_off, p_cur);
    fill_kernel<<<(E0 + 255) / 256, 256>>>(ei, p_cur, p_csr);

    // ---------- Layer 1 ----------
    {
        dim3 grid(NHID1 / 128, (NN + 127) / 128);
        tf32gemm<<<grid, 256>>>(x, W1, p_h1, NN, NF, NHID1);
    }
    node_scores<C1><<<(NN * NHEADS + 255) / 256, 256>>>(p_h1, a1_src, a1_dst, p_es, p_ed);
    gat_aggregate<C1, NHID1, 0><<<(NN + 7) / 8, 256>>>(p_off, p_csr, p_h1, p_es, p_ed, b1, p_agg1);

    // ---------- Layer 2 ----------
    {
        dim3 grid(NHID2 / 128, (NN + 127) / 128);
        tf32gemm<<<grid, 256>>>(p_agg1, W2, p_h2, NN, NHID1, NHID2);
    }
    node_scores<C2><<<(NN * NHEADS + 255) / 256, 256>>>(p_h2, a2_src, a2_dst, p_es, p_ed);
    gat_aggregate<C2, NHID2, 1><<<(NN + 7) / 8, 256>>>(p_off, p_csr, p_h2, p_es, p_ed, b2, out);
}

// round 10
// speedup vs baseline: 3.3050x; 1.0736x over previous
#include <cuda_runtime.h>
#include <cuda_fp16.h>
#include <cstdint>

#define NN      50000
#define NF      512
#define NHID1   256     // 8 heads * 32
#define NHID2   512     // 8 heads * 64
#define NCLS    64
#define NHEADS  8
#define C1      32
#define C2      64
#define E0      800000
#define NEG_SLOPE 0.2f

// ---------------- scratch (device globals; no allocs allowed) ----------------
__device__ __half g_h1[(size_t)NN * NHID1];
__device__ float  g_agg1[(size_t)NN * NHID1];
__device__ __half g_h2[(size_t)NN * NHID2];
__device__ float  g_es[(size_t)NN * NHEADS];
__device__ float  g_ed[(size_t)NN * NHEADS];
__device__ int    g_deg[NN];
__device__ int    g_off[NN + 1];
__device__ int    g_cur[NN];
__device__ int    g_csr[E0];                   // src indices sorted by dst

// ---------------- CSR build ----------------
__global__ void histogram_kernel(const int* __restrict__ ei, int* __restrict__ deg) {
    int e = blockIdx.x * blockDim.x + threadIdx.x;
    if (e >= E0) return;
    atomicAdd(deg + ei[E0 + e], 1);
}

__global__ void scan_kernel(const int* __restrict__ deg, int* __restrict__ off,
                            int* __restrict__ cur) {
    __shared__ int sh[1024];
    int t = threadIdx.x;
    const int CHUNK = (NN + 1023) / 1024;  // 49
    int beg = t * CHUNK;
    int end = min(beg + CHUNK, NN);
    int s = 0;
    for (int i = beg; i < end; i++) s += deg[i];
    sh[t] = s;
    __syncthreads();
    for (int st = 1; st < 1024; st <<= 1) {
        int a = (t >= st) ? sh[t - st] : 0;
        __syncthreads();
        sh[t] += a;
        __syncthreads();
    }
    int run = (t == 0) ? 0 : sh[t - 1];
    for (int i = beg; i < end; i++) {
        off[i] = run;
        cur[i] = run;
        run += deg[i];
    }
    if (t == 1023) off[NN] = E0;
}

__global__ void fill_kernel(const int* __restrict__ ei, int* __restrict__ cur,
                            int* __restrict__ csr) {
    int e = blockIdx.x * blockDim.x + threadIdx.x;
    if (e >= E0) return;
    int src = ei[e];
    int dst = ei[E0 + e];
    int pos = atomicAdd(cur + dst, 1);
    csr[pos] = src;
}

// ---------------- tf32 tensor-core GEMM, cp.async 2-stage pipeline ----------------
__device__ __forceinline__ uint32_t f2tf32(float f) {
    uint32_t u;
    asm("cvt.rna.tf32.f32 %0, %1;" : "=r"(u) : "f"(f));
    return u;
}

__device__ __forceinline__ void mma_tf32(float4& d, const uint32_t* a, const uint32_t* b) {
    asm volatile("mma.sync.aligned.m16n8k8.row.col.f32.tf32.tf32.f32 "
                 "{%0,%1,%2,%3}, {%4,%5,%6,%7}, {%8,%9}, {%0,%1,%2,%3};"
                 : "+f"(d.x), "+f"(d.y), "+f"(d.z), "+f"(d.w)
                 : "r"(a[0]), "r"(a[1]), "r"(a[2]), "r"(a[3]), "r"(b[0]), "r"(b[1]));
}

__device__ __forceinline__ void cp16(float* smem, const float* gmem, bool pred) {
    uint32_t s = (uint32_t)__cvta_generic_to_shared(smem);
    int sz = pred ? 16 : 0;
    asm volatile("cp.async.cg.shared.global [%0], [%1], 16, %2;"
                 :: "r"(s), "l"(gmem), "r"(sz));
}

// C[M,N](fp16) = A[M,K]*B[K,N]; 128x128x32 tiles, 8 warps, warp tile 64x32.
// As[m=128][k=32] stride 36 fp32 raw (cp.async fill, cvt at fragment load).
// Bs[k=32][n=128] stride 132 fp32 raw.
#define AS_STRIDE 36
#define BS_STRIDE 132
#define A_ELE (128 * AS_STRIDE)
#define B_ELE (32 * BS_STRIDE)
#define GEMM_SMEM (2 * (A_ELE + B_ELE) * 4)
__global__ void __launch_bounds__(256, 2)
tf32gemm(const float* __restrict__ A, const float* __restrict__ B,
         __half* __restrict__ C, int M, int K, int N) {
    extern __shared__ float sm[];
    float* As = sm;                 // 2 stages
    float* Bs = sm + 2 * A_ELE;
    int tid = threadIdx.x;
    int lane = tid & 31;
    int warp = tid >> 5;
    int wm = warp & 1;
    int wn = warp >> 1;
    int bm = blockIdx.y * 128, bn = blockIdx.x * 128;

    int gid = lane >> 2;
    int tig = lane & 3;

    // load indices
    int arow = tid >> 3;            // 0..31, +p*32
    int acol = (tid & 7) * 4;
    int bkr = tid >> 5;             // 0..7, +p*8
    int bnc = (tid & 31) * 4;

    float4 acc[4][4];
#pragma unroll
    for (int i = 0; i < 4; i++)
#pragma unroll
        for (int j = 0; j < 4; j++) acc[i][j] = make_float4(0.f, 0.f, 0.f, 0.f);

    int nIter = K >> 5;

    // prologue: stage 0
    {
        float* as = As;
        float* bs = Bs;
#pragma unroll
        for (int p = 0; p < 4; p++) {
            int row = arow + p * 32;
            cp16(&as[row * AS_STRIDE + acol], A + (size_t)(bm + row) * K + acol, bm + row < M);
        }
#pragma unroll
        for (int p = 0; p < 4; p++) {
            int k = bkr + p * 8;
            cp16(&bs[k * BS_STRIDE + bnc], B + (size_t)k * N + bn + bnc, true);
        }
        asm volatile("cp.async.commit_group;");
    }

    for (int it = 0; it < nIter; it++) {
        if (it + 1 < nIter) {
            int k0 = (it + 1) << 5;
            float* as = As + ((it + 1) & 1) * A_ELE;
            float* bs = Bs + ((it + 1) & 1) * B_ELE;
#pragma unroll
            for (int p = 0; p < 4; p++) {
                int row = arow + p * 32;
                cp16(&as[row * AS_STRIDE + acol], A + (size_t)(bm + row) * K + k0 + acol, bm + row < M);
            }
#pragma unroll
            for (int p = 0; p < 4; p++) {
                int k = bkr + p * 8;
                cp16(&bs[k * BS_STRIDE + bnc], B + (size_t)(k0 + k) * N + bn + bnc, true);
            }
            asm volatile("cp.async.commit_group;");
            asm volatile("cp.async.wait_group 1;");
        } else {
            asm volatile("cp.async.wait_group 0;");
        }
        __syncthreads();

        const float* as = As + (it & 1) * A_ELE;
        const float* bs = Bs + (it & 1) * B_ELE;
#pragma unroll
        for (int kk = 0; kk < 32; kk += 8) {
            uint32_t af[4][4];
            uint32_t bf[4][2];
#pragma unroll
            for (int mt = 0; mt < 4; mt++) {
                int m = wm * 64 + mt * 16;
                const float* a0 = &as[(m + gid) * AS_STRIDE + kk + tig];
                const float* a1 = &as[(m + gid + 8) * AS_STRIDE + kk + tig];
                af[mt][0] = f2tf32(a0[0]);
                af[mt][1] = f2tf32(a1[0]);
                af[mt][2] = f2tf32(a0[4]);
                af[mt][3] = f2tf32(a1[4]);
            }
#pragma unroll
            for (int nt = 0; nt < 4; nt++) {
                int n = wn * 32 + nt * 8;
                bf[nt][0] = f2tf32(bs[(kk + tig) * BS_STRIDE + n + gid]);
                bf[nt][1] = f2tf32(bs[(kk + tig + 4) * BS_STRIDE + n + gid]);
            }
#pragma unroll
            for (int mt = 0; mt < 4; mt++)
#pragma unroll
                for (int nt = 0; nt < 4; nt++)
                    mma_tf32(acc[mt][nt], af[mt], bf[nt]);
        }
        __syncthreads();
    }

#pragma unroll
    for (int mt = 0; mt < 4; mt++) {
        int row0 = bm + wm * 64 + mt * 16 + gid;
        int row1 = row0 + 8;
#pragma unroll
        for (int nt = 0; nt < 4; nt++) {
            int col = bn + wn * 32 + nt * 8 + tig * 2;
            if (row0 < M)
                *(__half2*)(C + (size_t)row0 * N + col) = __floats2half2_rn(acc[mt][nt].x, acc[mt][nt].y);
            if (row1 < M)
                *(__half2*)(C + (size_t)row1 * N + col) = __floats2half2_rn(acc[mt][nt].z, acc[mt][nt].w);
        }
    }
}

// ---------------- per-node attention scores (fp16 h) ----------------
template <int C>
__global__ void node_scores(const __half* __restrict__ hbuf,
                            const float* __restrict__ asrc,
                            const float* __restrict__ adst,
                            float* __restrict__ es, float* __restrict__ ed) {
    int idx = blockIdx.x * blockDim.x + threadIdx.x;
    if (idx >= NN * NHEADS) return;
    int n = idx >> 3, h = idx & 7;
    const __half2* hp = (const __half2*)(hbuf + (size_t)n * NHEADS * C + h * C);
    const float* ap = asrc + h * C;
    const float* dp = adst + h * C;
    float s = 0.f, d = 0.f;
#pragma unroll
    for (int c = 0; c < C / 2; c++) {
        float2 hv = __half22float2(hp[c]);
        s += hv.x * ap[2 * c] + hv.y * ap[2 * c + 1];
        d += hv.x * dp[2 * c] + hv.y * dp[2 * c + 1];
    }
    es[idx] = s;
    ed[idx] = d;
}

// ---------------- fused CSR aggregation (fp16 gather, fp32 accumulate) ----------------
// MODE 0: out fp32 = relu(agg + bias)        (layer 1)
// MODE 1: head-mean + bias + log_softmax fused in-warp, write final output (layer 2)
template <int C, int HID, int MODE>
__global__ void gat_aggregate(const int* __restrict__ off, const int* __restrict__ csr,
                              const __half* __restrict__ h,
                              const float* __restrict__ es, const float* __restrict__ ed,
                              const float* __restrict__ bias,
                              float* __restrict__ out) {
    constexpr int CPL = HID / 32;       // channels per lane (8 or 16)
    constexpr int NH = CPL / 8;         // uint4 (8 halves) per lane (1 or 2)
    int lane = threadIdx.x & 31;
    int node = blockIdx.x * 8 + (threadIdx.x >> 5);
    if (node >= NN) return;
    int chbase = lane * CPL;
    int hd = chbase / C;

    float edv = __ldg(ed + (size_t)node * 8 + hd);

    // self loop seed
    float a = __ldg(es + (size_t)node * 8 + hd) + edv;
    a = (a > 0.f) ? a : NEG_SLOPE * a;
    float w = __expf(a);
    float z = w;
    float acc[CPL];
    {
        const uint4* hp = (const uint4*)(h + (size_t)node * HID + chbase);
#pragma unroll
        for (int j = 0; j < NH; j++) {
            uint4 raw = __ldg(hp + j);
            const __half2* hh = (const __half2*)&raw;
#pragma unroll
            for (int q = 0; q < 4; q++) {
                float2 f = __half22float2(hh[q]);
                acc[j * 8 + 2 * q]     = w * f.x;
                acc[j * 8 + 2 * q + 1] = w * f.y;
            }
        }
    }

    int beg = __ldg(off + node), end = __ldg(off + node + 1);
    for (int i = beg; i < end; i++) {
        int src = __ldg(csr + i);
        float av = __ldg(es + (size_t)src * 8 + hd) + edv;
        av = (av > 0.f) ? av : NEG_SLOPE * av;
        float we = __expf(av);
        z += we;
        const uint4* sp = (const uint4*)(h + (size_t)src * HID + chbase);
#pragma unroll
        for (int j = 0; j < NH; j++) {
            uint4 raw = __ldg(sp + j);
            const __half2* hh = (const __half2*)&raw;
#pragma unroll
            for (int q = 0; q < 4; q++) {
                float2 f = __half22float2(hh[q]);
                acc[j * 8 + 2 * q]     += we * f.x;
                acc[j * 8 + 2 * q + 1] += we * f.y;
            }
        }
    }

    float inv = 1.f / z;

    if (MODE == 0) {
        float4* op = (float4*)(out + (size_t)node * HID + chbase);
#pragma unroll
        for (int j = 0; j < CPL / 4; j++) {
            float4 b = *(const float4*)(bias + chbase + j * 4);
            float4 o;
            o.x = fmaxf(acc[j * 4 + 0] * inv + b.x, 0.f);
            o.y = fmaxf(acc[j * 4 + 1] * inv + b.y, 0.f);
            o.z = fmaxf(acc[j * 4 + 2] * inv + b.z, 0.f);
            o.w = fmaxf(acc[j * 4 + 3] * inv + b.w, 0.f);
            op[j] = o;
        }
    } else {
        // ---- fused: head mean + bias + log_softmax (CPL==16, C==64) ----
        float v[16];
#pragma unroll
        for (int idx = 0; idx < 16; idx++) v[idx] = acc[idx] * inv;
#pragma unroll
        for (int m = 4; m <= 16; m <<= 1)
#pragma unroll
            for (int idx = 0; idx < 16; idx++)
                v[idx] += __shfl_xor_sync(0xffffffffu, v[idx], m);
        int mcls = (lane & 3) * 16;
#pragma unroll
        for (int idx = 0; idx < 16; idx++)
            v[idx] = v[idx] * 0.125f + __ldg(bias + mcls + idx);
        float mx = v[0];
#pragma unroll
        for (int idx = 1; idx < 16; idx++) mx = fmaxf(mx, v[idx]);
        mx = fmaxf(mx, __shfl_xor_sync(0xffffffffu, mx, 1));
        mx = fmaxf(mx, __shfl_xor_sync(0xffffffffu, mx, 2));
        float s = 0.f;
#pragma unroll
        for (int idx = 0; idx < 16; idx++) s += __expf(v[idx] - mx);
        s += __shfl_xor_sync(0xffffffffu, s, 1);
        s += __shfl_xor_sync(0xffffffffu, s, 2);
        float lg = mx + logf(s);
        if (lane < 4) {
            float4* op = (float4*)(out + (size_t)node * NCLS + lane * 16);
#pragma unroll
            for (int j = 0; j < 4; j++)
                op[j] = make_float4(v[j * 4] - lg, v[j * 4 + 1] - lg,
                                    v[j * 4 + 2] - lg, v[j * 4 + 3] - lg);
        }
    }
}

// ---------------- launch ----------------
extern "C" void kernel_launch(void* const* d_in, const int* in_sizes, int n_in,
                              void* d_out, int out_size) {
    const float* x      = (const float*)d_in[0];
    const int*   ei     = (const int*)d_in[1];
    const float* W1     = (const float*)d_in[2];
    const float* a1_src = (const float*)d_in[3];
    const float* a1_dst = (const float*)d_in[4];
    const float* b1     = (const float*)d_in[5];
    const float* W2     = (const float*)d_in[6];
    const float* a2_src = (const float*)d_in[7];
    const float* a2_dst = (const float*)d_in[8];
    const float* b2     = (const float*)d_in[9];
    float* out = (float*)d_out;

    __half *p_h1, *p_h2;
    float *p_agg1, *p_es, *p_ed;
    int *p_deg, *p_off, *p_cur, *p_csr;
    cudaGetSymbolAddress((void**)&p_h1,   g_h1);
    cudaGetSymbolAddress((void**)&p_agg1, g_agg1);
    cudaGetSymbolAddress((void**)&p_h2,   g_h2);
    cudaGetSymbolAddress((void**)&p_es,   g_es);
    cudaGetSymbolAddress((void**)&p_ed,   g_ed);
    cudaGetSymbolAddress((void**)&p_deg,  g_deg);
    cudaGetSymbolAddress((void**)&p_off,  g_off);
    cudaGetSymbolAddress((void**)&p_cur,  g_cur);
    cudaGetSymbolAddress((void**)&p_csr,  g_csr);

    static bool attr_done = false;
    if (!attr_done) {
        cudaFuncSetAttribute(tf32gemm, cudaFuncAttributeMaxDynamicSharedMemorySize, GEMM_SMEM);
        attr_done = true;
    }

    // ---------- CSR build (dst-sorted) ----------
    cudaMemsetAsync(p_deg, 0, NN * sizeof(int));
    histogram_kernel<<<(E0 + 255) / 256, 256>>>(ei, p_deg);
    scan_kernel<<<1, 1024>>>(p_deg, p_off, p_cur);
    fill_kernel<<<(E0 + 255) / 256, 256>>>(ei, p_cur, p_csr);

    // ---------- Layer 1 ----------
    {
        dim3 grid(NHID1 / 128, (NN + 127) / 128);
        tf32gemm<<<grid, 256, GEMM_SMEM>>>(x, W1, p_h1, NN, NF, NHID1);
    }
    node_scores<C1><<<(NN * NHEADS + 255) / 256, 256>>>(p_h1, a1_src, a1_dst, p_es, p_ed);
    gat_aggregate<C1, NHID1, 0><<<(NN + 7) / 8, 256>>>(p_off, p_csr, p_h1, p_es, p_ed, b1, p_agg1);

    // ---------- Layer 2 ----------
    {
        dim3 grid(NHID2 / 128, (NN + 127) / 128);
        tf32gemm<<<grid, 256, GEMM_SMEM>>>(p_agg1, W2, p_h2, NN, NHID1, NHID2);
    }
    node_scores<C2><<<(NN * NHEADS + 255) / 256, 256>>>(p_h2, a2_src, a2_dst, p_es, p_ed);
    gat_aggregate<C2, NHID2, 1><<<(NN + 7) / 8, 256>>>(p_off, p_csr, p_h2, p_es, p_ed, b2, out);
}

// round 11
// speedup vs baseline: 3.6729x; 1.1113x over previous
#include <cuda_runtime.h>
#include <cuda_fp16.h>
#include <cstdint>

#define NN      50000
#define NF      512
#define NHID1   256     // 8 heads * 32
#define NHID2   512     // 8 heads * 64
#define NCLS    64
#define NHEADS  8
#define C1      32
#define C2      64
#define E0      800000
#define NEG_SLOPE 0.2f

// ---------------- scratch (device globals; no allocs allowed) ----------------
__device__ __half g_h1[(size_t)NN * NHID1];
__device__ float  g_agg1[(size_t)NN * NHID1];
__device__ __half g_h2[(size_t)NN * NHID2];
__device__ float  g_es[(size_t)NN * NHEADS];
__device__ float  g_ed[(size_t)NN * NHEADS];
__device__ int    g_deg[NN];
__device__ int    g_off[NN + 1];
__device__ int    g_cur[NN];
__device__ int    g_csr[E0];                   // src indices sorted by dst

// ---------------- CSR build ----------------
__global__ void histogram_kernel(const int* __restrict__ ei, int* __restrict__ deg) {
    int e = blockIdx.x * blockDim.x + threadIdx.x;
    if (e >= E0) return;
    atomicAdd(deg + ei[E0 + e], 1);
}

__global__ void scan_kernel(const int* __restrict__ deg, int* __restrict__ off,
                            int* __restrict__ cur) {
    __shared__ int sh[1024];
    int t = threadIdx.x;
    const int CHUNK = (NN + 1023) / 1024;  // 49
    int beg = t * CHUNK;
    int end = min(beg + CHUNK, NN);
    int s = 0;
    for (int i = beg; i < end; i++) s += deg[i];
    sh[t] = s;
    __syncthreads();
    for (int st = 1; st < 1024; st <<= 1) {
        int a = (t >= st) ? sh[t - st] : 0;
        __syncthreads();
        sh[t] += a;
        __syncthreads();
    }
    int run = (t == 0) ? 0 : sh[t - 1];
    for (int i = beg; i < end; i++) {
        off[i] = run;
        cur[i] = run;
        run += deg[i];
    }
    if (t == 1023) off[NN] = E0;
}

__global__ void fill_kernel(const int* __restrict__ ei, int* __restrict__ cur,
                            int* __restrict__ csr) {
    int e = blockIdx.x * blockDim.x + threadIdx.x;
    if (e >= E0) return;
    int src = ei[e];
    int dst = ei[E0 + e];
    int pos = atomicAdd(cur + dst, 1);
    csr[pos] = src;
}

// ---------------- fp16 tensor-core GEMM (m16n8k16), cp.async 2-stage pipeline ----------------
__device__ __forceinline__ uint32_t pack_h2(float lo, float hi) {
    __half2 h = __floats2half2_rn(lo, hi);
    return *(uint32_t*)&h;
}

__device__ __forceinline__ void mma_f16(float4& d, const uint32_t* a, const uint32_t* b) {
    asm volatile("mma.sync.aligned.m16n8k16.row.col.f32.f16.f16.f32 "
                 "{%0,%1,%2,%3}, {%4,%5,%6,%7}, {%8,%9}, {%0,%1,%2,%3};"
                 : "+f"(d.x), "+f"(d.y), "+f"(d.z), "+f"(d.w)
                 : "r"(a[0]), "r"(a[1]), "r"(a[2]), "r"(a[3]), "r"(b[0]), "r"(b[1]));
}

__device__ __forceinline__ void cp16(float* smem, const float* gmem, bool pred) {
    uint32_t s = (uint32_t)__cvta_generic_to_shared(smem);
    int sz = pred ? 16 : 0;
    asm volatile("cp.async.cg.shared.global [%0], [%1], 16, %2;"
                 :: "r"(s), "l"(gmem), "r"(sz));
}

// C[M,N](fp16) = A[M,K]*B[K,N]; 128x128x32 tiles, 8 warps, warp tile 64x32.
// As[m=128][k=32] stride 40 fp32 raw (float2 fragment loads conflict-free).
// Bs[k=32][n=128] stride 132 fp32 raw (scalar fragment loads conflict-free).
#define AS_STRIDE 40
#define BS_STRIDE 132
#define A_ELE (128 * AS_STRIDE)
#define B_ELE (32 * BS_STRIDE)
#define GEMM_SMEM (2 * (A_ELE + B_ELE) * 4)
__global__ void __launch_bounds__(256, 2)
f16gemm(const float* __restrict__ A, const float* __restrict__ B,
        __half* __restrict__ C, int M, int K, int N) {
    extern __shared__ float sm[];
    float* As = sm;                 // 2 stages
    float* Bs = sm + 2 * A_ELE;
    int tid = threadIdx.x;
    int lane = tid & 31;
    int warp = tid >> 5;
    int wm = warp & 1;
    int wn = warp >> 1;
    int bm = blockIdx.y * 128, bn = blockIdx.x * 128;

    int gid = lane >> 2;
    int tig = lane & 3;

    // load indices
    int arow = tid >> 3;            // 0..31, +p*32
    int acol = (tid & 7) * 4;
    int bkr = tid >> 5;             // 0..7, +p*8
    int bnc = (tid & 31) * 4;

    float4 acc[4][4];
#pragma unroll
    for (int i = 0; i < 4; i++)
#pragma unroll
        for (int j = 0; j < 4; j++) acc[i][j] = make_float4(0.f, 0.f, 0.f, 0.f);

    int nIter = K >> 5;

    // prologue: stage 0
    {
#pragma unroll
        for (int p = 0; p < 4; p++) {
            int row = arow + p * 32;
            cp16(&As[row * AS_STRIDE + acol], A + (size_t)(bm + row) * K + acol, bm + row < M);
        }
#pragma unroll
        for (int p = 0; p < 4; p++) {
            int k = bkr + p * 8;
            cp16(&Bs[k * BS_STRIDE + bnc], B + (size_t)k * N + bn + bnc, true);
        }
        asm volatile("cp.async.commit_group;");
    }

    for (int it = 0; it < nIter; it++) {
        if (it + 1 < nIter) {
            int k0 = (it + 1) << 5;
            float* as = As + ((it + 1) & 1) * A_ELE;
            float* bs = Bs + ((it + 1) & 1) * B_ELE;
#pragma unroll
            for (int p = 0; p < 4; p++) {
                int row = arow + p * 32;
                cp16(&as[row * AS_STRIDE + acol], A + (size_t)(bm + row) * K + k0 + acol, bm + row < M);
            }
#pragma unroll
            for (int p = 0; p < 4; p++) {
                int k = bkr + p * 8;
                cp16(&bs[k * BS_STRIDE + bnc], B + (size_t)(k0 + k) * N + bn + bnc, true);
            }
            asm volatile("cp.async.commit_group;");
            asm volatile("cp.async.wait_group 1;");
        } else {
            asm volatile("cp.async.wait_group 0;");
        }
        __syncthreads();

        const float* as = As + (it & 1) * A_ELE;
        const float* bs = Bs + (it & 1) * B_ELE;
#pragma unroll
        for (int kk = 0; kk < 32; kk += 16) {
            uint32_t af[4][4];
            uint32_t bf[4][2];
#pragma unroll
            for (int mt = 0; mt < 4; mt++) {
                int m = wm * 64 + mt * 16;
                // a0: row gid,   k = kk+2tig..+1 ; a1: row gid+8 ; a2/a3: k+8
                float2 v0 = *(const float2*)&as[(m + gid)     * AS_STRIDE + kk + 2 * tig];
                float2 v1 = *(const float2*)&as[(m + gid + 8) * AS_STRIDE + kk + 2 * tig];
                float2 v2 = *(const float2*)&as[(m + gid)     * AS_STRIDE + kk + 2 * tig + 8];
                float2 v3 = *(const float2*)&as[(m + gid + 8) * AS_STRIDE + kk + 2 * tig + 8];
                af[mt][0] = pack_h2(v0.x, v0.y);
                af[mt][1] = pack_h2(v1.x, v1.y);
                af[mt][2] = pack_h2(v2.x, v2.y);
                af[mt][3] = pack_h2(v3.x, v3.y);
            }
#pragma unroll
            for (int nt = 0; nt < 4; nt++) {
                int n = wn * 32 + nt * 8;
                // b0: k = kk+2tig..+1, col n+gid ; b1: k+8
                float b00 = bs[(kk + 2 * tig)     * BS_STRIDE + n + gid];
                float b01 = bs[(kk + 2 * tig + 1) * BS_STRIDE + n + gid];
                float b10 = bs[(kk + 2 * tig + 8) * BS_STRIDE + n + gid];
                float b11 = bs[(kk + 2 * tig + 9) * BS_STRIDE + n + gid];
                bf[nt][0] = pack_h2(b00, b01);
                bf[nt][1] = pack_h2(b10, b11);
            }
#pragma unroll
            for (int mt = 0; mt < 4; mt++)
#pragma unroll
                for (int nt = 0; nt < 4; nt++)
                    mma_f16(acc[mt][nt], af[mt], bf[nt]);
        }
        __syncthreads();
    }

#pragma unroll
    for (int mt = 0; mt < 4; mt++) {
        int row0 = bm + wm * 64 + mt * 16 + gid;
        int row1 = row0 + 8;
#pragma unroll
        for (int nt = 0; nt < 4; nt++) {
            int col = bn + wn * 32 + nt * 8 + tig * 2;
            if (row0 < M)
                *(__half2*)(C + (size_t)row0 * N + col) = __floats2half2_rn(acc[mt][nt].x, acc[mt][nt].y);
            if (row1 < M)
                *(__half2*)(C + (size_t)row1 * N + col) = __floats2half2_rn(acc[mt][nt].z, acc[mt][nt].w);
        }
    }
}

// ---------------- per-node attention scores (fp16 h) ----------------
template <int C>
__global__ void node_scores(const __half* __restrict__ hbuf,
                            const float* __restrict__ asrc,
                            const float* __restrict__ adst,
                            float* __restrict__ es, float* __restrict__ ed) {
    int idx = blockIdx.x * blockDim.x + threadIdx.x;
    if (idx >= NN * NHEADS) return;
    int n = idx >> 3, h = idx & 7;
    const __half2* hp = (const __half2*)(hbuf + (size_t)n * NHEADS * C + h * C);
    const float* ap = asrc + h * C;
    const float* dp = adst + h * C;
    float s = 0.f, d = 0.f;
#pragma unroll
    for (int c = 0; c < C / 2; c++) {
        float2 hv = __half22float2(hp[c]);
        s += hv.x * ap[2 * c] + hv.y * ap[2 * c + 1];
        d += hv.x * dp[2 * c] + hv.y * dp[2 * c + 1];
    }
    es[idx] = s;
    ed[idx] = d;
}

// ---------------- fused CSR aggregation (fp16 gather, fp32 accumulate) ----------------
// MODE 0: out fp32 = relu(agg + bias)        (layer 1)
// MODE 1: head-mean + bias + log_softmax fused in-warp, write final output (layer 2)
template <int C, int HID, int MODE>
__global__ void gat_aggregate(const int* __restrict__ off, const int* __restrict__ csr,
                              const __half* __restrict__ h,
                              const float* __restrict__ es, const float* __restrict__ ed,
                              const float* __restrict__ bias,
                              float* __restrict__ out) {
    constexpr int CPL = HID / 32;       // channels per lane (8 or 16)
    constexpr int NH = CPL / 8;         // uint4 (8 halves) per lane (1 or 2)
    int lane = threadIdx.x & 31;
    int node = blockIdx.x * 8 + (threadIdx.x >> 5);
    if (node >= NN) return;
    int chbase = lane * CPL;
    int hd = chbase / C;

    float edv = __ldg(ed + (size_t)node * 8 + hd);

    // self loop seed
    float a = __ldg(es + (size_t)node * 8 + hd) + edv;
    a = (a > 0.f) ? a : NEG_SLOPE * a;
    float w = __expf(a);
    float z = w;
    float acc[CPL];
    {
        const uint4* hp = (const uint4*)(h + (size_t)node * HID + chbase);
#pragma unroll
        for (int j = 0; j < NH; j++) {
            uint4 raw = __ldg(hp + j);
            const __half2* hh = (const __half2*)&raw;
#pragma unroll
            for (int q = 0; q < 4; q++) {
                float2 f = __half22float2(hh[q]);
                acc[j * 8 + 2 * q]     = w * f.x;
                acc[j * 8 + 2 * q + 1] = w * f.y;
            }
        }
    }

    int beg = __ldg(off + node), end = __ldg(off + node + 1);
    for (int i = beg; i < end; i++) {
        int src = __ldg(csr + i);
        float av = __ldg(es + (size_t)src * 8 + hd) + edv;
        av = (av > 0.f) ? av : NEG_SLOPE * av;
        float we = __expf(av);
        z += we;
        const uint4* sp = (const uint4*)(h + (size_t)src * HID + chbase);
#pragma unroll
        for (int j = 0; j < NH; j++) {
            uint4 raw = __ldg(sp + j);
            const __half2* hh = (const __half2*)&raw;
#pragma unroll
            for (int q = 0; q < 4; q++) {
                float2 f = __half22float2(hh[q]);
                acc[j * 8 + 2 * q]     += we * f.x;
                acc[j * 8 + 2 * q + 1] += we * f.y;
            }
        }
    }

    float inv = 1.f / z;

    if (MODE == 0) {
        float4* op = (float4*)(out + (size_t)node * HID + chbase);
#pragma unroll
        for (int j = 0; j < CPL / 4; j++) {
            float4 b = *(const float4*)(bias + chbase + j * 4);
            float4 o;
            o.x = fmaxf(acc[j * 4 + 0] * inv + b.x, 0.f);
            o.y = fmaxf(acc[j * 4 + 1] * inv + b.y, 0.f);
            o.z = fmaxf(acc[j * 4 + 2] * inv + b.z, 0.f);
            o.w = fmaxf(acc[j * 4 + 3] * inv + b.w, 0.f);
            op[j] = o;
        }
    } else {
        // ---- fused: head mean + bias + log_softmax (CPL==16, C==64) ----
        float v[16];
#pragma unroll
        for (int idx = 0; idx < 16; idx++) v[idx] = acc[idx] * inv;
#pragma unroll
        for (int m = 4; m <= 16; m <<= 1)
#pragma unroll
            for (int idx = 0; idx < 16; idx++)
                v[idx] += __shfl_xor_sync(0xffffffffu, v[idx], m);
        int mcls = (lane & 3) * 16;
#pragma unroll
        for (int idx = 0; idx < 16; idx++)
            v[idx] = v[idx] * 0.125f + __ldg(bias + mcls + idx);
        float mx = v[0];
#pragma unroll
        for (int idx = 1; idx < 16; idx++) mx = fmaxf(mx, v[idx]);
        mx = fmaxf(mx, __shfl_xor_sync(0xffffffffu, mx, 1));
        mx = fmaxf(mx, __shfl_xor_sync(0xffffffffu, mx, 2));
        float s = 0.f;
#pragma unroll
        for (int idx = 0; idx < 16; idx++) s += __expf(v[idx] - mx);
        s += __shfl_xor_sync(0xffffffffu, s, 1);
        s += __shfl_xor_sync(0xffffffffu, s, 2);
        float lg = mx + logf(s);
        if (lane < 4) {
            float4* op = (float4*)(out + (size_t)node * NCLS + lane * 16);
#pragma unroll
            for (int j = 0; j < 4; j++)
                op[j] = make_float4(v[j * 4] - lg, v[j * 4 + 1] - lg,
                                    v[j * 4 + 2] - lg, v[j * 4 + 3] - lg);
        }
    }
}

// ---------------- launch ----------------
extern "C" void kernel_launch(void* const* d_in, const int* in_sizes, int n_in,
                              void* d_out, int out_size) {
    const float* x      = (const float*)d_in[0];
    const int*   ei     = (const int*)d_in[1];
    const float* W1     = (const float*)d_in[2];
    const float* a1_src = (const float*)d_in[3];
    const float* a1_dst = (const float*)d_in[4];
    const float* b1     = (const float*)d_in[5];
    const float* W2     = (const float*)d_in[6];
    const float* a2_src = (const float*)d_in[7];
    const float* a2_dst = (const float*)d_in[8];
    const float* b2     = (const float*)d_in[9];
    float* out = (float*)d_out;

    __half *p_h1, *p_h2;
    float *p_agg1, *p_es, *p_ed;
    int *p_deg, *p_off, *p_cur, *p_csr;
    cudaGetSymbolAddress((void**)&p_h1,   g_h1);
    cudaGetSymbolAddress((void**)&p_agg1, g_agg1);
    cudaGetSymbolAddress((void**)&p_h2,   g_h2);
    cudaGetSymbolAddress((void**)&p_es,   g_es);
    cudaGetSymbolAddress((void**)&p_ed,   g_ed);
    cudaGetSymbolAddress((void**)&p_deg,  g_deg);
    cudaGetSymbolAddress((void**)&p_off,  g_off);
    cudaGetSymbolAddress((void**)&p_cur,  g_cur);
    cudaGetSymbolAddress((void**)&p_csr,  g_csr);

    static bool attr_done = false;
    if (!attr_done) {
        cudaFuncSetAttribute(f16gemm, cudaFuncAttributeMaxDynamicSharedMemorySize, GEMM_SMEM);
        attr_done = true;
    }

    // ---------- CSR build (dst-sorted) ----------
    cudaMemsetAsync(p_deg, 0, NN * sizeof(int));
    histogram_kernel<<<(E0 + 255) / 256, 256>>>(ei, p_deg);
    scan_kernel<<<1, 1024>>>(p_deg, p_off, p_cur);
    fill_kernel<<<(E0 + 255) / 256, 256>>>(ei, p_cur, p_csr);

    // ---------- Layer 1 ----------
    {
        dim3 grid(NHID1 / 128, (NN + 127) / 128);
        f16gemm<<<grid, 256, GEMM_SMEM>>>(x, W1, p_h1, NN, NF, NHID1);
    }
    node_scores<C1><<<(NN * NHEADS + 255) / 256, 256>>>(p_h1, a1_src, a1_dst, p_es, p_ed);
    gat_aggregate<C1, NHID1, 0><<<(NN + 7) / 8, 256>>>(p_off, p_csr, p_h1, p_es, p_ed, b1, p_agg1);

    // ---------- Layer 2 ----------
    {
        dim3 grid(NHID2 / 128, (NN + 127) / 128);
        f16gemm<<<grid, 256, GEMM_SMEM>>>(p_agg1, W2, p_h2, NN, NHID1, NHID2);
    }
    node_scores<C2><<<(NN * NHEADS + 255) / 256, 256>>>(p_h2, a2_src, a2_dst, p_es, p_ed);
    gat_aggregate<C2, NHID2, 1><<<(NN + 7) / 8, 256>>>(p_off, p_csr, p_h2, p_es, p_ed, b2, out);
}